// round 10
// baseline (speedup 1.0000x reference)
#include <cuda_runtime.h>
#include <cuda_fp16.h>
#include <cstdint>

// Attention O = softmax(QK^T)V, [B=4,H=16,S=2048,D=64], fp32.
// R9: softmax row-sums (l) computed by tensor core via ones-column in V padding;
//     O-rescale skipped when running max unchanged; faster preconv.
// 2-pass QK^T (Qh*Kh + Ql*Kh), fp16 PV, cp.async double-buffered, exp2 domain.

#define S_LEN 2048
#define DHD 64
#define BM 128
#define BN 64
#define NT (S_LEN / BN)     // 32
#define STR 72              // smem row stride in halfs
#define TOTE (64LL * S_LEN * DHD)   // elements per tensor (BH=64)
#define LOG2E 1.44269504088896340736f

// smem offsets (halfs)
#define O_QH 0
#define O_QL (BM * STR)                 // 9216
#define O_B0 (2 * BM * STR)             // 18432
#define BUFH (2 * BN * STR)             // 9216 halfs per buffer (KH,VS)
#define SMEM_HALFS (O_B0 + 2 * BUFH)    // 36864
#define SMEM_BYTES (SMEM_HALFS * 2)     // 73728

__device__ __half g_KH[TOTE];
__device__ __half g_VS[TOTE];

static __device__ __forceinline__ uint32_t sa(const void* p) {
    uint32_t a;
    asm("{\n\t.reg .u64 t;\n\tcvta.to.shared.u64 t, %1;\n\tcvt.u32.u64 %0, t;\n\t}"
        : "=r"(a) : "l"(p));
    return a;
}
static __device__ __forceinline__ float ex2(float x) {
    float r;
    asm("ex2.approx.f32 %0, %1;" : "=f"(r) : "f"(x));
    return r;
}
static __device__ __forceinline__ void ldx4(uint32_t* r, uint32_t a) {
    asm volatile("ldmatrix.sync.aligned.m8n8.x4.shared.b16 {%0,%1,%2,%3}, [%4];"
                 : "=r"(r[0]), "=r"(r[1]), "=r"(r[2]), "=r"(r[3]) : "r"(a));
}
static __device__ __forceinline__ void ldx4t(uint32_t* r, uint32_t a) {
    asm volatile("ldmatrix.sync.aligned.m8n8.x4.trans.shared.b16 {%0,%1,%2,%3}, [%4];"
                 : "=r"(r[0]), "=r"(r[1]), "=r"(r[2]), "=r"(r[3]) : "r"(a));
}
static __device__ __forceinline__ void ldx2t(uint32_t* r, uint32_t a) {
    asm volatile("ldmatrix.sync.aligned.m8n8.x2.trans.shared.b16 {%0,%1}, [%2];"
                 : "=r"(r[0]), "=r"(r[1]) : "r"(a));
}
static __device__ __forceinline__ void mma16816(float* d, const uint32_t* a, const uint32_t* b) {
    asm volatile("mma.sync.aligned.m16n8k16.row.col.f32.f16.f16.f32 "
                 "{%0,%1,%2,%3},{%4,%5,%6,%7},{%8,%9},{%0,%1,%2,%3};"
                 : "+f"(d[0]), "+f"(d[1]), "+f"(d[2]), "+f"(d[3])
                 : "r"(a[0]), "r"(a[1]), "r"(a[2]), "r"(a[3]), "r"(b[0]), "r"(b[1]));
}
static __device__ __forceinline__ void cpasync16(uint32_t dst, const void* src) {
    asm volatile("cp.async.cg.shared.global [%0], [%1], 16;" :: "r"(dst), "l"(src) : "memory");
}
#define CP_COMMIT() asm volatile("cp.async.commit_group;" ::: "memory")
#define CP_WAIT0()  asm volatile("cp.async.wait_group 0;" ::: "memory")

// split (a,b) into packed hi half2 and residual-lo half2
static __device__ __forceinline__ void split2(float a, float b, uint32_t& hi, uint32_t& lo) {
    __half ha = __float2half_rn(a), hb = __float2half_rn(b);
    __half2 h = __halves2half2(ha, hb);
    __half2 l = __floats2half2_rn(a - __half2float(ha), b - __half2float(hb));
    hi = *(uint32_t*)&h;
    lo = *(uint32_t*)&l;
}

// ---- pass 1: K,V fp32 -> fp16 scratch (2 chunks/thread for MLP) ----
__global__ void __launch_bounds__(256)
preconv_kernel(const float* __restrict__ K, const float* __restrict__ V) {
    const long long gid = (long long)blockIdx.x * 256 + threadIdx.x;
    const long long HALF = TOTE / 2;
    long long ia = gid * 4;
    long long ib = ia + HALF;
    if (ib >= TOTE) return;
    float4 ka = *(const float4*)(K + ia);
    float4 va = *(const float4*)(V + ia);
    float4 kb = *(const float4*)(K + ib);
    float4 vb = *(const float4*)(V + ib);
    __half2 t0 = __floats2half2_rn(ka.x, ka.y), t1 = __floats2half2_rn(ka.z, ka.w);
    *(uint32_t*)(g_KH + ia) = *(uint32_t*)&t0; *(uint32_t*)(g_KH + ia + 2) = *(uint32_t*)&t1;
    t0 = __floats2half2_rn(va.x, va.y); t1 = __floats2half2_rn(va.z, va.w);
    *(uint32_t*)(g_VS + ia) = *(uint32_t*)&t0; *(uint32_t*)(g_VS + ia + 2) = *(uint32_t*)&t1;
    t0 = __floats2half2_rn(kb.x, kb.y); t1 = __floats2half2_rn(kb.z, kb.w);
    *(uint32_t*)(g_KH + ib) = *(uint32_t*)&t0; *(uint32_t*)(g_KH + ib + 2) = *(uint32_t*)&t1;
    t0 = __floats2half2_rn(vb.x, vb.y); t1 = __floats2half2_rn(vb.z, vb.w);
    *(uint32_t*)(g_VS + ib) = *(uint32_t*)&t0; *(uint32_t*)(g_VS + ib + 2) = *(uint32_t*)&t1;
}

// ---- pass 2: flash attention ----
__global__ void __launch_bounds__(256, 2)
attn_mma_kernel(const float* __restrict__ Q, float* __restrict__ Out)
{
    extern __shared__ __half sm[];
    const uint32_t sb = sa(sm);

    const int tid  = threadIdx.x;
    const int wid  = tid >> 5;
    const int lane = tid & 31;
    const int l15  = lane & 15;

    const long long base = (long long)blockIdx.y * (S_LEN * DHD);
    const float*  Qg  = Q + base + (long long)blockIdx.x * (BM * DHD);
    const __half* KHg = g_KH + base;
    const __half* VSg = g_VS + base;
    float*        Og  = Out + base + (long long)blockIdx.x * (BM * DHD);

    // cp.async chunk mapping: 2 chunks per thread per matrix (512 chunks each)
    const int c0r = tid >> 3, c0c = (tid & 7) * 8;          // chunk tid
    const int c1r = (tid + 256) >> 3, c1c = c0c;            // chunk tid+256

    // ---- prologue: issue tile-0 copies ----
    {
        uint32_t bk = sb + (uint32_t)(O_B0) * 2;
        cpasync16(bk + (uint32_t)(c0r * STR + c0c) * 2, KHg + c0r * DHD + c0c);
        cpasync16(bk + (uint32_t)(c1r * STR + c1c) * 2, KHg + c1r * DHD + c1c);
        bk += BN * STR * 2;
        cpasync16(bk + (uint32_t)(c0r * STR + c0c) * 2, VSg + c0r * DHD + c0c);
        cpasync16(bk + (uint32_t)(c1r * STR + c1c) * 2, VSg + c1r * DHD + c1c);
        CP_COMMIT();
    }

    // ---- V ones-column padding: both buffers, rows 0..63, cols 64..71 ----
    // (cp.async never touches cols 64-71; written once, col 64 = 1.0, rest 0)
    {
        int row = tid >> 2;            // 0..63
        int cg  = tid & 3;             // half2 group in cols 64..71
        __half2 pad = (cg == 0) ? __halves2half2(__float2half(1.0f), __float2half(0.0f))
                                : __halves2half2(__float2half(0.0f), __float2half(0.0f));
        int vbase0 = O_B0 + BN * STR;              // V in buffer 0
        int vbase1 = O_B0 + BUFH + BN * STR;       // V in buffer 1
        *(__half2*)(&sm[vbase0 + row * STR + 64 + cg * 2]) = pad;
        *(__half2*)(&sm[vbase1 + row * STR + 64 + cg * 2]) = pad;
    }

    // ---- Q tile: load, scale by log2e, hi/lo split -> smem ----
    #pragma unroll
    for (int i = 0; i < 8; i++) {
        int idx = tid * 4 + i * 1024;     // 0..8191
        int r = idx >> 6, c = idx & 63;
        float4 q = *(const float4*)(Qg + r * DHD + c);
        q.x *= LOG2E; q.y *= LOG2E; q.z *= LOG2E; q.w *= LOG2E;
        uint32_t h0, l0, h1, l1;
        split2(q.x, q.y, h0, l0);
        split2(q.z, q.w, h1, l1);
        *(uint32_t*)(&sm[O_QH + r * STR + c])     = h0;
        *(uint32_t*)(&sm[O_QH + r * STR + c + 2]) = h1;
        *(uint32_t*)(&sm[O_QL + r * STR + c])     = l0;
        *(uint32_t*)(&sm[O_QL + r * STR + c + 2]) = l1;
    }

    float o[8][4];
    #pragma unroll
    for (int nn = 0; nn < 8; nn++)
        #pragma unroll
        for (int j = 0; j < 4; j++) o[nn][j] = 0.0f;
    float ol[4] = {0.0f, 0.0f, 0.0f, 0.0f};   // ones-column accumulator (col 64 = l)
    float m_lo = -1.0e30f, m_hi = -1.0e30f;

    for (int t = 0; t < NT; t++) {
        CP_WAIT0();            // tile t landed (only group outstanding)
        __syncthreads();       // collective: tile t visible; buffer swap safe

        // issue tile t+1 into the other buffer (overlaps compute below)
        if (t + 1 < NT) {
            const long long kg = (long long)(t + 1) * BN * DHD;
            uint32_t bk = sb + (uint32_t)(O_B0 + ((t + 1) & 1) * BUFH) * 2;
            cpasync16(bk + (uint32_t)(c0r * STR + c0c) * 2, KHg + kg + c0r * DHD + c0c);
            cpasync16(bk + (uint32_t)(c1r * STR + c1c) * 2, KHg + kg + c1r * DHD + c1c);
            bk += BN * STR * 2;
            cpasync16(bk + (uint32_t)(c0r * STR + c0c) * 2, VSg + kg + c0r * DHD + c0c);
            cpasync16(bk + (uint32_t)(c1r * STR + c1c) * 2, VSg + kg + c1r * DHD + c1c);
            CP_COMMIT();
        }

        const int kh = O_B0 + (t & 1) * BUFH;
        const int vs = kh + BN * STR;

        // ---- QK^T: 2-pass (Qh*Kh + Ql*Kh = Q * fp16(K)), log2 domain ----
        float s[8][4];
        #pragma unroll
        for (int nn = 0; nn < 8; nn++)
            #pragma unroll
            for (int j = 0; j < 4; j++) s[nn][j] = 0.0f;

        #pragma unroll
        for (int kk = 0; kk < 4; kk++) {
            const int ar = wid * 16 + (lane & 7) + ((lane >> 3) & 1) * 8;
            const int ac = kk * 16 + (lane >> 4) * 8;
            uint32_t ah[4], al[4];
            ldx4(ah, sb + (uint32_t)(O_QH + ar * STR + ac) * 2);
            ldx4(al, sb + (uint32_t)(O_QL + ar * STR + ac) * 2);
            // K fragment pair via x4: lanes 0-15 -> frag nn, 16-31 -> frag nn+1
            const int kr = (lane & 7) + ((lane >> 4) & 1) * 8;
            const int kc = kk * 16 + ((lane >> 3) & 1) * 8;
            #pragma unroll
            for (int nn = 0; nn < 8; nn += 2) {
                uint32_t bh4[4];
                ldx4(bh4, sb + (uint32_t)(kh + (nn * 8 + kr) * STR + kc) * 2);
                mma16816(s[nn],     ah, bh4);
                mma16816(s[nn],     al, bh4);
                mma16816(s[nn + 1], ah, bh4 + 2);
                mma16816(s[nn + 1], al, bh4 + 2);
            }
        }

        // ---- online softmax in log2 domain (rows: lo = lane>>2, hi = +8) ----
        float mt_lo = -1.0e30f, mt_hi = -1.0e30f;
        #pragma unroll
        for (int nn = 0; nn < 8; nn++) {
            mt_lo = fmaxf(mt_lo, fmaxf(s[nn][0], s[nn][1]));
            mt_hi = fmaxf(mt_hi, fmaxf(s[nn][2], s[nn][3]));
        }
        mt_lo = fmaxf(mt_lo, __shfl_xor_sync(0xffffffffu, mt_lo, 1));
        mt_lo = fmaxf(mt_lo, __shfl_xor_sync(0xffffffffu, mt_lo, 2));
        mt_hi = fmaxf(mt_hi, __shfl_xor_sync(0xffffffffu, mt_hi, 1));
        mt_hi = fmaxf(mt_hi, __shfl_xor_sync(0xffffffffu, mt_hi, 2));

        // rescale only when the running max actually moved (rare after warmup)
        if (mt_lo > m_lo || mt_hi > m_hi) {
            const float mn_lo = fmaxf(m_lo, mt_lo);
            const float mn_hi = fmaxf(m_hi, mt_hi);
            const float sc_lo = ex2(m_lo - mn_lo);
            const float sc_hi = ex2(m_hi - mn_hi);
            m_lo = mn_lo; m_hi = mn_hi;
            #pragma unroll
            for (int nn = 0; nn < 8; nn++) {
                o[nn][0] *= sc_lo; o[nn][1] *= sc_lo;
                o[nn][2] *= sc_hi; o[nn][3] *= sc_hi;
            }
            ol[0] *= sc_lo; ol[1] *= sc_lo;
            ol[2] *= sc_hi; ol[3] *= sc_hi;
        }

        uint32_t pa[8], pb[8];
        #pragma unroll
        for (int nn = 0; nn < 8; nn++) {
            float p0 = ex2(s[nn][0] - m_lo);
            float p1 = ex2(s[nn][1] - m_lo);
            float p2 = ex2(s[nn][2] - m_hi);
            float p3 = ex2(s[nn][3] - m_hi);
            __half2 hA = __floats2half2_rn(p0, p1);
            __half2 hB = __floats2half2_rn(p2, p3);
            pa[nn] = *(uint32_t*)&hA;
            pb[nn] = *(uint32_t*)&hB;
        }

        // ---- PV: O += P * V; l accumulated via ones-column (cols 64-71) ----
        #pragma unroll
        for (int kk = 0; kk < 4; kk++) {
            uint32_t a[4] = { pa[2 * kk], pb[2 * kk], pa[2 * kk + 1], pb[2 * kk + 1] };
            const int vr = kk * 16 + l15;
            const int vc = ((lane >> 4) & 1) * 8;
            #pragma unroll
            for (int nn = 0; nn < 8; nn += 2) {
                uint32_t bv4[4];
                ldx4t(bv4, sb + (uint32_t)(vs + vr * STR + nn * 8 + vc) * 2);
                mma16816(o[nn],     a, bv4);
                mma16816(o[nn + 1], a, bv4 + 2);
            }
            uint32_t bl2[2];
            ldx2t(bl2, sb + (uint32_t)(vs + vr * STR + 64) * 2);
            mma16816(ol, a, bl2);
        }
    }

    // ---- epilogue: l = ones-column (col 64, quad lane 0), normalize, store ----
    const float l_lo = __shfl_sync(0xffffffffu, ol[0], lane & ~3);
    const float l_hi = __shfl_sync(0xffffffffu, ol[2], lane & ~3);
    const float inv_lo = 1.0f / l_lo;
    const float inv_hi = 1.0f / l_hi;

    const int r_lo = wid * 16 + (lane >> 2);
    const int r_hi = r_lo + 8;
    #pragma unroll
    for (int nn = 0; nn < 8; nn++) {
        int d0 = nn * 8 + (lane & 3) * 2;
        float2 wlo = { o[nn][0] * inv_lo, o[nn][1] * inv_lo };
        float2 whi = { o[nn][2] * inv_hi, o[nn][3] * inv_hi };
        *(float2*)(Og + (long long)r_lo * DHD + d0) = wlo;
        *(float2*)(Og + (long long)r_hi * DHD + d0) = whi;
    }
}

extern "C" void kernel_launch(void* const* d_in, const int* in_sizes, int n_in,
                              void* d_out, int out_size) {
    const float* Q = (const float*)d_in[0];
    const float* K = (const float*)d_in[1];
    const float* V = (const float*)d_in[2];
    float* O = (float*)d_out;

    const int BH = in_sizes[0] / (S_LEN * DHD);  // 64

    preconv_kernel<<<(unsigned)(TOTE / 8 / 256), 256>>>(K, V);

    cudaFuncSetAttribute(attn_mma_kernel,
                         cudaFuncAttributeMaxDynamicSharedMemorySize, SMEM_BYTES);
    dim3 grid(S_LEN / BM, BH);
    attn_mma_kernel<<<grid, 256, SMEM_BYTES>>>(Q, O);
}

// round 11
// speedup vs baseline: 1.5173x; 1.5173x over previous
#include <cuda_runtime.h>
#include <cuda_fp16.h>
#include <cstdint>

// Attention O = softmax(QK^T)V, [B=4,H=16,S=2048,D=64], fp32.
// R10 = R8 revert (known-good 281.5us) + fast preconv only.
// 2-pass QK^T (Qh*Kh + Ql*Kh), fp16 PV, cp.async double-buffered, exp2 domain,
// log2e folded into Q, K/V frag loads via ldmatrix.x4.

#define S_LEN 2048
#define DHD 64
#define BM 128
#define BN 64
#define NT (S_LEN / BN)     // 32
#define STR 72              // smem row stride in halfs
#define TOTE (64LL * S_LEN * DHD)   // elements per tensor (BH=64)
#define LOG2E 1.44269504088896340736f

// smem offsets (halfs)
#define O_QH 0
#define O_QL (BM * STR)                 // 9216
#define O_B0 (2 * BM * STR)             // 18432
#define BUFH (2 * BN * STR)             // 9216 halfs per buffer (KH,VS)
#define SMEM_HALFS (O_B0 + 2 * BUFH)    // 36864
#define SMEM_BYTES (SMEM_HALFS * 2)     // 73728

__device__ __half g_KH[TOTE];
__device__ __half g_VS[TOTE];

static __device__ __forceinline__ uint32_t sa(const void* p) {
    uint32_t a;
    asm("{\n\t.reg .u64 t;\n\tcvta.to.shared.u64 t, %1;\n\tcvt.u32.u64 %0, t;\n\t}"
        : "=r"(a) : "l"(p));
    return a;
}
static __device__ __forceinline__ float ex2(float x) {
    float r;
    asm("ex2.approx.f32 %0, %1;" : "=f"(r) : "f"(x));
    return r;
}
static __device__ __forceinline__ void ldx4(uint32_t* r, uint32_t a) {
    asm volatile("ldmatrix.sync.aligned.m8n8.x4.shared.b16 {%0,%1,%2,%3}, [%4];"
                 : "=r"(r[0]), "=r"(r[1]), "=r"(r[2]), "=r"(r[3]) : "r"(a));
}
static __device__ __forceinline__ void ldx4t(uint32_t* r, uint32_t a) {
    asm volatile("ldmatrix.sync.aligned.m8n8.x4.trans.shared.b16 {%0,%1,%2,%3}, [%4];"
                 : "=r"(r[0]), "=r"(r[1]), "=r"(r[2]), "=r"(r[3]) : "r"(a));
}
static __device__ __forceinline__ void mma16816(float* d, const uint32_t* a, const uint32_t* b) {
    asm volatile("mma.sync.aligned.m16n8k16.row.col.f32.f16.f16.f32 "
                 "{%0,%1,%2,%3},{%4,%5,%6,%7},{%8,%9},{%0,%1,%2,%3};"
                 : "+f"(d[0]), "+f"(d[1]), "+f"(d[2]), "+f"(d[3])
                 : "r"(a[0]), "r"(a[1]), "r"(a[2]), "r"(a[3]), "r"(b[0]), "r"(b[1]));
}
static __device__ __forceinline__ void cpasync16(uint32_t dst, const void* src) {
    asm volatile("cp.async.cg.shared.global [%0], [%1], 16;" :: "r"(dst), "l"(src) : "memory");
}
#define CP_COMMIT() asm volatile("cp.async.commit_group;" ::: "memory")
#define CP_WAIT0()  asm volatile("cp.async.wait_group 0;" ::: "memory")

// split (a,b) into packed hi half2 and residual-lo half2
static __device__ __forceinline__ void split2(float a, float b, uint32_t& hi, uint32_t& lo) {
    __half ha = __float2half_rn(a), hb = __float2half_rn(b);
    __half2 h = __halves2half2(ha, hb);
    __half2 l = __floats2half2_rn(a - __half2float(ha), b - __half2float(hb));
    hi = *(uint32_t*)&h;
    lo = *(uint32_t*)&l;
}

// ---- pass 1: K,V fp32 -> fp16 scratch (2 chunks/thread for MLP) ----
__global__ void __launch_bounds__(256)
preconv_kernel(const float* __restrict__ K, const float* __restrict__ V) {
    const long long gid = (long long)blockIdx.x * 256 + threadIdx.x;
    const long long HALF = TOTE / 2;
    long long ia = gid * 4;
    long long ib = ia + HALF;
    if (ib >= TOTE) return;
    float4 ka = *(const float4*)(K + ia);
    float4 va = *(const float4*)(V + ia);
    float4 kb = *(const float4*)(K + ib);
    float4 vb = *(const float4*)(V + ib);
    __half2 t0 = __floats2half2_rn(ka.x, ka.y), t1 = __floats2half2_rn(ka.z, ka.w);
    *(uint32_t*)(g_KH + ia) = *(uint32_t*)&t0; *(uint32_t*)(g_KH + ia + 2) = *(uint32_t*)&t1;
    t0 = __floats2half2_rn(va.x, va.y); t1 = __floats2half2_rn(va.z, va.w);
    *(uint32_t*)(g_VS + ia) = *(uint32_t*)&t0; *(uint32_t*)(g_VS + ia + 2) = *(uint32_t*)&t1;
    t0 = __floats2half2_rn(kb.x, kb.y); t1 = __floats2half2_rn(kb.z, kb.w);
    *(uint32_t*)(g_KH + ib) = *(uint32_t*)&t0; *(uint32_t*)(g_KH + ib + 2) = *(uint32_t*)&t1;
    t0 = __floats2half2_rn(vb.x, vb.y); t1 = __floats2half2_rn(vb.z, vb.w);
    *(uint32_t*)(g_VS + ib) = *(uint32_t*)&t0; *(uint32_t*)(g_VS + ib + 2) = *(uint32_t*)&t1;
}

// ---- pass 2: flash attention (byte-identical to R8) ----
__global__ void __launch_bounds__(256, 2)
attn_mma_kernel(const float* __restrict__ Q, float* __restrict__ Out)
{
    extern __shared__ __half sm[];
    const uint32_t sb = sa(sm);

    const int tid  = threadIdx.x;
    const int wid  = tid >> 5;
    const int lane = tid & 31;
    const int l15  = lane & 15;

    const long long base = (long long)blockIdx.y * (S_LEN * DHD);
    const float*  Qg  = Q + base + (long long)blockIdx.x * (BM * DHD);
    const __half* KHg = g_KH + base;
    const __half* VSg = g_VS + base;
    float*        Og  = Out + base + (long long)blockIdx.x * (BM * DHD);

    // cp.async chunk mapping: 2 chunks per thread per matrix (512 chunks each)
    const int c0r = tid >> 3, c0c = (tid & 7) * 8;          // chunk tid
    const int c1r = (tid + 256) >> 3, c1c = c0c;            // chunk tid+256

    // ---- prologue: issue tile-0 copies, then convert Q (scaled by log2e) ----
    {
        uint32_t bk = sb + (uint32_t)(O_B0) * 2;
        cpasync16(bk + (uint32_t)(c0r * STR + c0c) * 2, KHg + c0r * DHD + c0c);
        cpasync16(bk + (uint32_t)(c1r * STR + c1c) * 2, KHg + c1r * DHD + c1c);
        bk += BN * STR * 2;
        cpasync16(bk + (uint32_t)(c0r * STR + c0c) * 2, VSg + c0r * DHD + c0c);
        cpasync16(bk + (uint32_t)(c1r * STR + c1c) * 2, VSg + c1r * DHD + c1c);
        CP_COMMIT();
    }

    #pragma unroll
    for (int i = 0; i < 8; i++) {
        int idx = tid * 4 + i * 1024;     // 0..8191
        int r = idx >> 6, c = idx & 63;
        float4 q = *(const float4*)(Qg + r * DHD + c);
        q.x *= LOG2E; q.y *= LOG2E; q.z *= LOG2E; q.w *= LOG2E;
        uint32_t h0, l0, h1, l1;
        split2(q.x, q.y, h0, l0);
        split2(q.z, q.w, h1, l1);
        *(uint32_t*)(&sm[O_QH + r * STR + c])     = h0;
        *(uint32_t*)(&sm[O_QH + r * STR + c + 2]) = h1;
        *(uint32_t*)(&sm[O_QL + r * STR + c])     = l0;
        *(uint32_t*)(&sm[O_QL + r * STR + c + 2]) = l1;
    }

    float o[8][4];
    #pragma unroll
    for (int nn = 0; nn < 8; nn++)
        #pragma unroll
        for (int j = 0; j < 4; j++) o[nn][j] = 0.0f;
    float m_lo = -1.0e30f, m_hi = -1.0e30f, l_lo = 0.0f, l_hi = 0.0f;

    for (int t = 0; t < NT; t++) {
        CP_WAIT0();            // tile t landed (only group outstanding)
        __syncthreads();       // collective: tile t visible; buffer swap safe

        // issue tile t+1 into the other buffer (overlaps compute below)
        if (t + 1 < NT) {
            const long long kg = (long long)(t + 1) * BN * DHD;
            uint32_t bk = sb + (uint32_t)(O_B0 + ((t + 1) & 1) * BUFH) * 2;
            cpasync16(bk + (uint32_t)(c0r * STR + c0c) * 2, KHg + kg + c0r * DHD + c0c);
            cpasync16(bk + (uint32_t)(c1r * STR + c1c) * 2, KHg + kg + c1r * DHD + c1c);
            bk += BN * STR * 2;
            cpasync16(bk + (uint32_t)(c0r * STR + c0c) * 2, VSg + kg + c0r * DHD + c0c);
            cpasync16(bk + (uint32_t)(c1r * STR + c1c) * 2, VSg + kg + c1r * DHD + c1c);
            CP_COMMIT();
        }

        const int kh = O_B0 + (t & 1) * BUFH;
        const int vs = kh + BN * STR;

        // ---- QK^T: 2-pass (Qh*Kh + Ql*Kh = Q * fp16(K)), log2 domain ----
        float s[8][4];
        #pragma unroll
        for (int nn = 0; nn < 8; nn++)
            #pragma unroll
            for (int j = 0; j < 4; j++) s[nn][j] = 0.0f;

        #pragma unroll
        for (int kk = 0; kk < 4; kk++) {
            const int ar = wid * 16 + (lane & 7) + ((lane >> 3) & 1) * 8;
            const int ac = kk * 16 + (lane >> 4) * 8;
            uint32_t ah[4], al[4];
            ldx4(ah, sb + (uint32_t)(O_QH + ar * STR + ac) * 2);
            ldx4(al, sb + (uint32_t)(O_QL + ar * STR + ac) * 2);
            // K fragment pair via x4: lanes 0-15 -> frag nn, 16-31 -> frag nn+1
            const int kr = (lane & 7) + ((lane >> 4) & 1) * 8;
            const int kc = kk * 16 + ((lane >> 3) & 1) * 8;
            #pragma unroll
            for (int nn = 0; nn < 8; nn += 2) {
                uint32_t bh4[4];
                ldx4(bh4, sb + (uint32_t)(kh + (nn * 8 + kr) * STR + kc) * 2);
                mma16816(s[nn],     ah, bh4);
                mma16816(s[nn],     al, bh4);
                mma16816(s[nn + 1], ah, bh4 + 2);
                mma16816(s[nn + 1], al, bh4 + 2);
            }
        }

        // ---- online softmax in log2 domain (rows: lo = lane>>2, hi = +8) ----
        float mt_lo = -1.0e30f, mt_hi = -1.0e30f;
        #pragma unroll
        for (int nn = 0; nn < 8; nn++) {
            mt_lo = fmaxf(mt_lo, fmaxf(s[nn][0], s[nn][1]));
            mt_hi = fmaxf(mt_hi, fmaxf(s[nn][2], s[nn][3]));
        }
        mt_lo = fmaxf(mt_lo, __shfl_xor_sync(0xffffffffu, mt_lo, 1));
        mt_lo = fmaxf(mt_lo, __shfl_xor_sync(0xffffffffu, mt_lo, 2));
        mt_hi = fmaxf(mt_hi, __shfl_xor_sync(0xffffffffu, mt_hi, 1));
        mt_hi = fmaxf(mt_hi, __shfl_xor_sync(0xffffffffu, mt_hi, 2));

        const float mn_lo = fmaxf(m_lo, mt_lo);
        const float mn_hi = fmaxf(m_hi, mt_hi);
        const float sc_lo = ex2(m_lo - mn_lo);
        const float sc_hi = ex2(m_hi - mn_hi);
        m_lo = mn_lo; m_hi = mn_hi;
        l_lo *= sc_lo; l_hi *= sc_hi;

        uint32_t pa[8], pb[8];
        #pragma unroll
        for (int nn = 0; nn < 8; nn++) {
            float p0 = ex2(s[nn][0] - mn_lo);
            float p1 = ex2(s[nn][1] - mn_lo);
            float p2 = ex2(s[nn][2] - mn_hi);
            float p3 = ex2(s[nn][3] - mn_hi);
            l_lo += p0 + p1;
            l_hi += p2 + p3;
            __half2 hA = __floats2half2_rn(p0, p1);
            __half2 hB = __floats2half2_rn(p2, p3);
            pa[nn] = *(uint32_t*)&hA;
            pb[nn] = *(uint32_t*)&hB;
            o[nn][0] *= sc_lo; o[nn][1] *= sc_lo;
            o[nn][2] *= sc_hi; o[nn][3] *= sc_hi;
        }

        // ---- PV: O += P * V (B frag pairs via ldmatrix.x4.trans) ----
        #pragma unroll
        for (int kk = 0; kk < 4; kk++) {
            uint32_t a[4] = { pa[2 * kk], pb[2 * kk], pa[2 * kk + 1], pb[2 * kk + 1] };
            // lanes 0-15 -> d-cols nn*8.., lanes 16-31 -> d-cols nn*8+8..
            const int vr = kk * 16 + l15;
            const int vc = ((lane >> 4) & 1) * 8;
            #pragma unroll
            for (int nn = 0; nn < 8; nn += 2) {
                uint32_t bv4[4];
                ldx4t(bv4, sb + (uint32_t)(vs + vr * STR + nn * 8 + vc) * 2);
                mma16816(o[nn],     a, bv4);
                mma16816(o[nn + 1], a, bv4 + 2);
            }
        }
    }

    // ---- epilogue: reduce l across lane%4, normalize, store ----
    l_lo += __shfl_xor_sync(0xffffffffu, l_lo, 1);
    l_lo += __shfl_xor_sync(0xffffffffu, l_lo, 2);
    l_hi += __shfl_xor_sync(0xffffffffu, l_hi, 1);
    l_hi += __shfl_xor_sync(0xffffffffu, l_hi, 2);
    const float inv_lo = 1.0f / l_lo;
    const float inv_hi = 1.0f / l_hi;

    const int r_lo = wid * 16 + (lane >> 2);
    const int r_hi = r_lo + 8;
    #pragma unroll
    for (int nn = 0; nn < 8; nn++) {
        int d0 = nn * 8 + (lane & 3) * 2;
        float2 wlo = { o[nn][0] * inv_lo, o[nn][1] * inv_lo };
        float2 whi = { o[nn][2] * inv_hi, o[nn][3] * inv_hi };
        *(float2*)(Og + (long long)r_lo * DHD + d0) = wlo;
        *(float2*)(Og + (long long)r_hi * DHD + d0) = whi;
    }
}

extern "C" void kernel_launch(void* const* d_in, const int* in_sizes, int n_in,
                              void* d_out, int out_size) {
    const float* Q = (const float*)d_in[0];
    const float* K = (const float*)d_in[1];
    const float* V = (const float*)d_in[2];
    float* O = (float*)d_out;

    const int BH = in_sizes[0] / (S_LEN * DHD);  // 64

    preconv_kernel<<<(unsigned)(TOTE / 8 / 256), 256>>>(K, V);

    cudaFuncSetAttribute(attn_mma_kernel,
                         cudaFuncAttributeMaxDynamicSharedMemorySize, SMEM_BYTES);
    dim3 grid(S_LEN / BM, BH);
    attn_mma_kernel<<<grid, 256, SMEM_BYTES>>>(Q, O);
}